// round 2
// baseline (speedup 1.0000x reference)
#include <cuda_runtime.h>
#include <math.h>

#define N_LEVELS 16
#define HASHMAP_SIZE 32768
#define HASH_MASK 32767u
#define NPTS 524288
#define P1 2654435761u
#define P2 805459861u
#define N_DENSE 9            // levels 0..8 use dense z-paired tables

// Materialized per-level hashed tables: [16][32768] x float2  (4 MB)
__device__ float2 g_tables[N_LEVELS * HASHMAP_SIZE];

// Dense z-paired tables for levels 0..8.
// Upper-bound dims R_UB[l] = res_ub+2 (res <= floor(16*2^(l/3))):
//   l : res<= : R_UB : R_UB^3
//   0 :  16   : 18   : 5832
//   1 :  20   : 22   : 10648
//   2 :  25   : 27   : 19683
//   3 :  32   : 34   : 39304
//   4 :  40   : 42   : 74088
//   5 :  50   : 52   : 140608
//   6 :  64   : 66   : 287496
//   7 :  80   : 82   : 551368
//   8 : 101   : 103  : 1092727
#define DENSE_TOTAL 2221754
__device__ float4 g_dense[DENSE_TOTAL];

__constant__ int c_zero = 0;   // (unused; keeps nvcc happy about empty cmem use)

struct Params {
    float res[N_LEVELS];
    int   R[N_DENSE];       // runtime dims (res+1) per dense level
};

// compile-time offsets into g_dense (exclusive prefix of R_UB^3)
#define DOFF0 0
#define DOFF1 5832
#define DOFF2 16480
#define DOFF3 36163
#define DOFF4 75467
#define DOFF5 149555
#define DOFF6 290163
#define DOFF7 577659
#define DOFF8 1129027
__device__ __constant__ int DOFF[N_DENSE + 1] = {
    DOFF0, DOFF1, DOFF2, DOFF3, DOFF4, DOFF5, DOFF6, DOFF7, DOFF8, DENSE_TOTAL
};

// ---------------------------------------------------------------------------
// Kernel 1: tables[l][s][:] = A[l][s][0:4] @ B[l][0:4][0:2]
// ---------------------------------------------------------------------------
__global__ void __launch_bounds__(256) build_tables_kernel(
    const float* __restrict__ A, const float* __restrict__ B) {
    int idx = blockIdx.x * blockDim.x + threadIdx.x;   // 0 .. 524287
    int l = idx >> 15;
    float4 a = __ldg(reinterpret_cast<const float4*>(A) + idx);
    const float* b = B + l * 8;                        // [r][f] row-major
    float f0 = a.x * b[0];
    f0 = fmaf(a.y, b[2], f0);
    f0 = fmaf(a.z, b[4], f0);
    f0 = fmaf(a.w, b[6], f0);
    float f1 = a.x * b[1];
    f1 = fmaf(a.y, b[3], f1);
    f1 = fmaf(a.z, b[5], f1);
    f1 = fmaf(a.w, b[7], f1);
    g_tables[idx] = make_float2(f0, f1);
}

// ---------------------------------------------------------------------------
// Kernel 2: build dense z-paired tables for levels 0..8
//   dense[l][x][y][z] = ( T_l[h(x,y,z)&m], T_l[h(x,y,z+1)&m] )  as float4
// ---------------------------------------------------------------------------
__global__ void __launch_bounds__(256) build_dense_kernel(Params p) {
    int idx = blockIdx.x * blockDim.x + threadIdx.x;
    if (idx >= DENSE_TOTAL) return;
    // find level (9-way compare, unrolled)
    int l = 0;
#pragma unroll
    for (int k = 1; k < N_DENSE; k++)
        if (idx >= DOFF[k]) l = k;
    unsigned local = (unsigned)(idx - DOFF[l]);
    unsigned R = (unsigned)p.R[l];
    unsigned RR = R * R;
    if (local >= RR * R) return;          // UB padding gap
    unsigned x = local / RR;
    unsigned rem = local - x * RR;
    unsigned y = rem / R;
    unsigned z = rem - y * R;

    unsigned hxy = x ^ (y * P1);
    unsigned h0 = hxy ^ (z * P2);
    unsigned h1 = hxy ^ ((z + 1u) * P2);
    const float2* tab = g_tables + (l << 15);
    float2 v0 = __ldg(&tab[h0 & HASH_MASK]);
    float2 v1 = __ldg(&tab[h1 & HASH_MASK]);
    g_dense[idx] = make_float4(v0.x, v0.y, v1.x, v1.y);
}

// ---------------------------------------------------------------------------
// Kernel 3: encode. Levels 0..8 via dense float4 (4 gathers),
//           levels 9..15 via hashed float2 (8 gathers).
// ---------------------------------------------------------------------------
__device__ __forceinline__ float2 lerp2(float2 a, float2 b, float t) {
    return make_float2(fmaf(t, b.x - a.x, a.x),
                       fmaf(t, b.y - a.y, a.y));
}

__global__ void __launch_bounds__(256) encode_kernel(
    const float* __restrict__ x, float* __restrict__ out, Params p) {
    int n = blockIdx.x * blockDim.x + threadIdx.x;

    float xn0 = (__ldg(&x[3 * n + 0]) + 1.0f) * 0.5f;
    float xn1 = (__ldg(&x[3 * n + 1]) + 1.0f) * 0.5f;
    float xn2 = (__ldg(&x[3 * n + 2]) + 1.0f) * 0.5f;

    float4* o = reinterpret_cast<float4*>(out + (size_t)n * 32);
    float2 prev;   // result of even level, stored together with odd level

#pragma unroll
    for (int l = 0; l < N_LEVELS; l++) {
        float r = p.res[l];
        float fx = xn0 * r, fy = xn1 * r, fz = xn2 * r;
        float flx = floorf(fx), fly = floorf(fy), flz = floorf(fz);
        float wx = fx - flx, wy = fy - fly, wz = fz - flz;
        unsigned ix = (unsigned)flx;
        unsigned iy = (unsigned)fly;
        unsigned iz = (unsigned)flz;

        float2 rr;
        if (l < N_DENSE) {
            // dense path: 4 x float4, z-pair packed
            int R = p.R[l];
            int RR = R * R;
            const float4* D = g_dense + DOFF[l];
            int base = ((int)ix * R + (int)iy) * R + (int)iz;
            float4 p00 = __ldg(&D[base]);
            float4 p10 = __ldg(&D[base + RR]);
            float4 p01 = __ldg(&D[base + R]);
            float4 p11 = __ldg(&D[base + RR + R]);
            // z-lerp inside each float4
            float2 m00 = make_float2(fmaf(wz, p00.z - p00.x, p00.x),
                                     fmaf(wz, p00.w - p00.y, p00.y));
            float2 m10 = make_float2(fmaf(wz, p10.z - p10.x, p10.x),
                                     fmaf(wz, p10.w - p10.y, p10.y));
            float2 m01 = make_float2(fmaf(wz, p01.z - p01.x, p01.x),
                                     fmaf(wz, p01.w - p01.y, p01.y));
            float2 m11 = make_float2(fmaf(wz, p11.z - p11.x, p11.x),
                                     fmaf(wz, p11.w - p11.y, p11.y));
            float2 q0 = lerp2(m00, m10, wx);
            float2 q1 = lerp2(m01, m11, wx);
            rr = lerp2(q0, q1, wy);
        } else {
            // hash path: 8 x float2
            unsigned hy0 = iy * P1;
            unsigned hy1 = hy0 + P1;
            unsigned hz0 = iz * P2;
            unsigned hz1 = hz0 + P2;
            unsigned x0 = ix, x1 = ix + 1u;

            unsigned b00 = x0 ^ hy0;
            unsigned b10 = x1 ^ hy0;
            unsigned b01 = x0 ^ hy1;
            unsigned b11 = x1 ^ hy1;

            const float2* tab = g_tables + (l << 15);
            float2 c000 = __ldg(&tab[(b00 ^ hz0) & HASH_MASK]);
            float2 c100 = __ldg(&tab[(b10 ^ hz0) & HASH_MASK]);
            float2 c010 = __ldg(&tab[(b01 ^ hz0) & HASH_MASK]);
            float2 c110 = __ldg(&tab[(b11 ^ hz0) & HASH_MASK]);
            float2 c001 = __ldg(&tab[(b00 ^ hz1) & HASH_MASK]);
            float2 c101 = __ldg(&tab[(b10 ^ hz1) & HASH_MASK]);
            float2 c011 = __ldg(&tab[(b01 ^ hz1) & HASH_MASK]);
            float2 c111 = __ldg(&tab[(b11 ^ hz1) & HASH_MASK]);

            float2 m00 = lerp2(c000, c100, wx);
            float2 m10 = lerp2(c010, c110, wx);
            float2 m01 = lerp2(c001, c101, wx);
            float2 m11 = lerp2(c011, c111, wx);
            float2 mm0 = lerp2(m00, m10, wy);
            float2 mm1 = lerp2(m01, m11, wy);
            rr = lerp2(mm0, mm1, wz);
        }

        if ((l & 1) == 0) {
            prev = rr;
        } else {
            o[l >> 1] = make_float4(prev.x, prev.y, rr.x, rr.y);
        }
    }
}

// ---------------------------------------------------------------------------
// Launch
// ---------------------------------------------------------------------------
extern "C" void kernel_launch(void* const* d_in, const int* in_sizes, int n_in,
                              void* d_out, int out_size) {
    const float* x = (const float*)d_in[0];        // [524288, 3]
    const float* A = (const float*)d_in[1];        // [16, 32768, 4]
    const float* B = (const float*)d_in[2];        // [16, 4, 2]
    float* out = (float*)d_out;                    // [524288, 32]

    // Replicate numpy's resolution computation bit-exactly.
    Params p;
    double b = exp((log(512.0) - log(16.0)) / 15.0);
    for (int l = 0; l < N_LEVELS; l++) {
        double bl;
        if (l == 0)      bl = 1.0;
        else if (l == 1) bl = b;
        else if (l == 2) bl = b * b;
        else             bl = pow(b, (double)l);
        p.res[l] = (float)floor(16.0 * bl);
    }
    for (int l = 0; l < N_DENSE; l++)
        p.R[l] = (int)p.res[l] + 1;

    build_tables_kernel<<<(N_LEVELS * HASHMAP_SIZE) / 256, 256>>>(A, B);
    build_dense_kernel<<<(DENSE_TOTAL + 255) / 256, 256>>>(p);
    encode_kernel<<<NPTS / 256, 256>>>(x, out, p);
}

// round 3
// speedup vs baseline: 1.6627x; 1.6627x over previous
#include <cuda_runtime.h>
#include <math.h>

#define N_LEVELS 16
#define HASHMAP_SIZE 32768
#define HASH_MASK 32767u
#define NPTS 524288
#define P1 2654435761u
#define P2 805459861u

// Materialized per-level tables: [16][32768] x float2  (4 MB, L2-resident)
__device__ float2 g_tables[N_LEVELS * HASHMAP_SIZE];

struct ResParams { float res[N_LEVELS]; };

// ---------------------------------------------------------------------------
// Kernel 1: tables[l][s][:] = A[l][s][0:4] @ B[l][0:4][0:2]
// ---------------------------------------------------------------------------
__global__ void __launch_bounds__(256) build_tables_kernel(
    const float* __restrict__ A, const float* __restrict__ B) {
    int idx = blockIdx.x * blockDim.x + threadIdx.x;   // 0 .. 524287
    int l = idx >> 15;
    float4 a = __ldg(reinterpret_cast<const float4*>(A) + idx);
    const float* b = B + l * 8;                        // [r][f] row-major
    float f0 = a.x * b[0];
    f0 = fmaf(a.y, b[2], f0);
    f0 = fmaf(a.z, b[4], f0);
    f0 = fmaf(a.w, b[6], f0);
    float f1 = a.x * b[1];
    f1 = fmaf(a.y, b[3], f1);
    f1 = fmaf(a.z, b[5], f1);
    f1 = fmaf(a.w, b[7], f1);
    g_tables[idx] = make_float2(f0, f1);
}

// ---------------------------------------------------------------------------
// Kernel 2: hash-grid trilinear encode.
// One thread per (point, half): thread handles 8 consecutive levels and
// writes 4 contiguous float4s. 2x threads vs one-thread-per-point ->
// lower reg pressure, better latency hiding on the gather chains.
// ---------------------------------------------------------------------------
__device__ __forceinline__ float2 lerp2(float2 a, float2 b, float t) {
    return make_float2(fmaf(t, b.x - a.x, a.x),
                       fmaf(t, b.y - a.y, a.y));
}

__global__ void __launch_bounds__(256) encode_kernel(
    const float* __restrict__ x, float* __restrict__ out, ResParams p) {
    int tid = blockIdx.x * blockDim.x + threadIdx.x;   // 0 .. 2*NPTS-1
    int n    = tid >> 1;
    int half = tid & 1;
    int l0   = half << 3;                              // 0 or 8

    float xn0 = (__ldg(&x[3 * n + 0]) + 1.0f) * 0.5f;
    float xn1 = (__ldg(&x[3 * n + 1]) + 1.0f) * 0.5f;
    float xn2 = (__ldg(&x[3 * n + 2]) + 1.0f) * 0.5f;

    float4* o = reinterpret_cast<float4*>(out + (size_t)n * 32) + (half << 2);
    float2 prev;

#pragma unroll
    for (int k = 0; k < 8; k++) {
        int l = l0 + k;
        float r = p.res[l];
        float fx = xn0 * r, fy = xn1 * r, fz = xn2 * r;
        float flx = floorf(fx), fly = floorf(fy), flz = floorf(fz);
        float wx = fx - flx, wy = fy - fly, wz = fz - flz;
        unsigned ix = (unsigned)flx;
        unsigned iy = (unsigned)fly;
        unsigned iz = (unsigned)flz;

        unsigned hy0 = iy * P1;
        unsigned hy1 = hy0 + P1;
        unsigned hz0 = iz * P2;
        unsigned hz1 = hz0 + P2;
        unsigned x0 = ix, x1 = ix + 1u;

        unsigned b00 = x0 ^ hy0;
        unsigned b10 = x1 ^ hy0;
        unsigned b01 = x0 ^ hy1;
        unsigned b11 = x1 ^ hy1;

        const float2* tab = g_tables + (l << 15);
        float2 c000 = __ldg(&tab[(b00 ^ hz0) & HASH_MASK]);
        float2 c100 = __ldg(&tab[(b10 ^ hz0) & HASH_MASK]);
        float2 c010 = __ldg(&tab[(b01 ^ hz0) & HASH_MASK]);
        float2 c110 = __ldg(&tab[(b11 ^ hz0) & HASH_MASK]);
        float2 c001 = __ldg(&tab[(b00 ^ hz1) & HASH_MASK]);
        float2 c101 = __ldg(&tab[(b10 ^ hz1) & HASH_MASK]);
        float2 c011 = __ldg(&tab[(b01 ^ hz1) & HASH_MASK]);
        float2 c111 = __ldg(&tab[(b11 ^ hz1) & HASH_MASK]);

        float2 m00 = lerp2(c000, c100, wx);
        float2 m10 = lerp2(c010, c110, wx);
        float2 m01 = lerp2(c001, c101, wx);
        float2 m11 = lerp2(c011, c111, wx);
        float2 mm0 = lerp2(m00, m10, wy);
        float2 mm1 = lerp2(m01, m11, wy);
        float2 rr  = lerp2(mm0, mm1, wz);

        if ((k & 1) == 0) {
            prev = rr;
        } else {
            o[k >> 1] = make_float4(prev.x, prev.y, rr.x, rr.y);
        }
    }
}

// ---------------------------------------------------------------------------
// Launch
// ---------------------------------------------------------------------------
extern "C" void kernel_launch(void* const* d_in, const int* in_sizes, int n_in,
                              void* d_out, int out_size) {
    const float* x = (const float*)d_in[0];        // [524288, 3]
    const float* A = (const float*)d_in[1];        // [16, 32768, 4]
    const float* B = (const float*)d_in[2];        // [16, 4, 2]
    float* out = (float*)d_out;                    // [524288, 32]

    // Replicate numpy's resolution computation bit-exactly.
    ResParams p;
    double b = exp((log(512.0) - log(16.0)) / 15.0);
    for (int l = 0; l < N_LEVELS; l++) {
        double bl;
        if (l == 0)      bl = 1.0;
        else if (l == 1) bl = b;
        else if (l == 2) bl = b * b;
        else             bl = pow(b, (double)l);
        p.res[l] = (float)floor(16.0 * bl);
    }

    build_tables_kernel<<<(N_LEVELS * HASHMAP_SIZE) / 256, 256>>>(A, B);
    encode_kernel<<<(2 * NPTS) / 256, 256>>>(x, out, p);
}

// round 4
// speedup vs baseline: 1.8004x; 1.0828x over previous
#include <cuda_runtime.h>
#include <math.h>

#define N_LEVELS 16
#define HASHMAP_SIZE 32768
#define HASH_MASK 32767u
#define NPTS 524288
#define P1 2654435761u
#define P2 805459861u

// Materialized per-level tables: [16][32768] x float2 (4 MB), 16B-aligned so
// aligned index-pairs can be fetched as one float4.
__device__ __align__(16) float2 g_tables[N_LEVELS * HASHMAP_SIZE];

struct ResParams { float res[N_LEVELS]; };

// ---------------------------------------------------------------------------
// Kernel 1: tables[l][s][:] = A[l][s][0:4] @ B[l][0:4][0:2]
// ---------------------------------------------------------------------------
__global__ void __launch_bounds__(256) build_tables_kernel(
    const float* __restrict__ A, const float* __restrict__ B) {
    int idx = blockIdx.x * blockDim.x + threadIdx.x;   // 0 .. 524287
    int l = idx >> 15;
    float4 a = __ldg(reinterpret_cast<const float4*>(A) + idx);
    const float* b = B + l * 8;                        // [r][f] row-major
    float f0 = a.x * b[0];
    f0 = fmaf(a.y, b[2], f0);
    f0 = fmaf(a.z, b[4], f0);
    f0 = fmaf(a.w, b[6], f0);
    float f1 = a.x * b[1];
    f1 = fmaf(a.y, b[3], f1);
    f1 = fmaf(a.z, b[5], f1);
    f1 = fmaf(a.w, b[7], f1);
    g_tables[idx] = make_float2(f0, f1);
}

// ---------------------------------------------------------------------------
// Kernel 2: hash-grid trilinear encode, thread = (point, half of levels).
// x-corner pairs: hash uses prime 1 for x, so for even ix the two x-corner
// indices are (i0, i0^1) -> one aligned float4 load instead of two float2s.
// ---------------------------------------------------------------------------
__device__ __forceinline__ float2 lerp2(float2 a, float2 b, float t) {
    return make_float2(fmaf(t, b.x - a.x, a.x),
                       fmaf(t, b.y - a.y, a.y));
}

__global__ void __launch_bounds__(256) encode_kernel(
    const float* __restrict__ x, float* __restrict__ out, ResParams p) {
    int tid = blockIdx.x * blockDim.x + threadIdx.x;   // 0 .. 2*NPTS-1
    int n    = tid >> 1;
    int half = tid & 1;
    int l0   = half << 3;                              // 0 or 8

    float xn0 = (__ldg(&x[3 * n + 0]) + 1.0f) * 0.5f;
    float xn1 = (__ldg(&x[3 * n + 1]) + 1.0f) * 0.5f;
    float xn2 = (__ldg(&x[3 * n + 2]) + 1.0f) * 0.5f;

    float4* o = reinterpret_cast<float4*>(out + (size_t)n * 32) + (half << 2);
    float2 prev;

#pragma unroll
    for (int k = 0; k < 8; k++) {
        int l = l0 + k;
        float r = p.res[l];
        float fx = xn0 * r, fy = xn1 * r, fz = xn2 * r;
        float flx = floorf(fx), fly = floorf(fy), flz = floorf(fz);
        float wx = fx - flx, wy = fy - fly, wz = fz - flz;
        unsigned ix = (unsigned)flx;
        unsigned iy = (unsigned)fly;
        unsigned iz = (unsigned)flz;

        unsigned hy0 = iy * P1;
        unsigned hy1 = hy0 + P1;
        unsigned hz0 = iz * P2;
        unsigned hz1 = hz0 + P2;
        // r for the 4 (y,z) corner combos
        unsigned r00 = hy0 ^ hz0;
        unsigned r10 = hy1 ^ hz0;
        unsigned r01 = hy0 ^ hz1;
        unsigned r11 = hy1 ^ hz1;

        const float2* tab = g_tables + (l << 15);

        // corner values: aYZ = x-corner 0, bYZ = x-corner 1
        float2 a00, b00, a10, b10, a01, b01, a11, b11;

        if ((ix & 1u) == 0u) {
            // even ix: x-pair = (i0, i0^1) -> one float4 per (y,z) combo
            const float4* tab4 = reinterpret_cast<const float4*>(tab);
#define LOAD_PAIR(RYZ, AV, BV)                                              \
            {                                                               \
                unsigned i0 = (ix ^ (RYZ)) & HASH_MASK;                     \
                float4 q = __ldg(&tab4[i0 >> 1]);                           \
                float2 qlo = make_float2(q.x, q.y);                         \
                float2 qhi = make_float2(q.z, q.w);                         \
                bool sw = (i0 & 1u) != 0u;                                  \
                AV = sw ? qhi : qlo;                                        \
                BV = sw ? qlo : qhi;                                        \
            }
            LOAD_PAIR(r00, a00, b00)
            LOAD_PAIR(r10, a10, b10)
            LOAD_PAIR(r01, a01, b01)
            LOAD_PAIR(r11, a11, b11)
#undef LOAD_PAIR
        } else {
            unsigned x1 = ix + 1u;
            a00 = __ldg(&tab[(ix ^ r00) & HASH_MASK]);
            b00 = __ldg(&tab[(x1 ^ r00) & HASH_MASK]);
            a10 = __ldg(&tab[(ix ^ r10) & HASH_MASK]);
            b10 = __ldg(&tab[(x1 ^ r10) & HASH_MASK]);
            a01 = __ldg(&tab[(ix ^ r01) & HASH_MASK]);
            b01 = __ldg(&tab[(x1 ^ r01) & HASH_MASK]);
            a11 = __ldg(&tab[(ix ^ r11) & HASH_MASK]);
            b11 = __ldg(&tab[(x1 ^ r11) & HASH_MASK]);
        }

        float2 m00 = lerp2(a00, b00, wx);
        float2 m10 = lerp2(a10, b10, wx);
        float2 m01 = lerp2(a01, b01, wx);
        float2 m11 = lerp2(a11, b11, wx);
        float2 mm0 = lerp2(m00, m10, wy);
        float2 mm1 = lerp2(m01, m11, wy);
        float2 rr  = lerp2(mm0, mm1, wz);

        if ((k & 1) == 0) {
            prev = rr;
        } else {
            o[k >> 1] = make_float4(prev.x, prev.y, rr.x, rr.y);
        }
    }
}

// ---------------------------------------------------------------------------
// Launch
// ---------------------------------------------------------------------------
extern "C" void kernel_launch(void* const* d_in, const int* in_sizes, int n_in,
                              void* d_out, int out_size) {
    const float* x = (const float*)d_in[0];        // [524288, 3]
    const float* A = (const float*)d_in[1];        // [16, 32768, 4]
    const float* B = (const float*)d_in[2];        // [16, 4, 2]
    float* out = (float*)d_out;                    // [524288, 32]

    // Replicate numpy's resolution computation bit-exactly.
    ResParams p;
    double b = exp((log(512.0) - log(16.0)) / 15.0);
    for (int l = 0; l < N_LEVELS; l++) {
        double bl;
        if (l == 0)      bl = 1.0;
        else if (l == 1) bl = b;
        else if (l == 2) bl = b * b;
        else             bl = pow(b, (double)l);
        p.res[l] = (float)floor(16.0 * bl);
    }

    build_tables_kernel<<<(N_LEVELS * HASHMAP_SIZE) / 256, 256>>>(A, B);
    encode_kernel<<<(2 * NPTS) / 256, 256>>>(x, out, p);
}